// round 10
// baseline (speedup 1.0000x reference)
#include <cuda_runtime.h>
#include <cuda_bf16.h>
#include <cuda_fp16.h>
#include <cstdint>

#define NN 100000
#define NE 1600000
#define DD 128
#define NB ((NN + 1023) / 1024)       // 98 scan blocks
#define NTILE ((NN + 127) / 128)      // 782 GEMM tiles
#define NTA 132                       // gemm tiles in launch 1 (with hist)
#define NTS 50                        // gemm tiles in launch 2 (with scan)
#define NTB (NTILE - NTA - NTS)       // 600 gemm tiles in launch 3 (with permute)
#define NHB ((NE + 2047) / 2048)      // 782 hist blocks (ILP8)
#define NPERM ((NE + 2047) / 2048)    // 782 permute blocks (ILP8)
#define ROWPAD 136                    // bf16 elems per SMEM row (272B, conflict-free)

typedef unsigned long long ull;

// ---------------- scratch (__device__ globals; zero-initialized at load) ----------------
__device__ __half g_hf[(size_t)NN * DD];   // 25.6 MB fp16 h = x @ W.T + b
__device__ int    g_deg[NN];               // invariant: 0 at kernel_launch entry
__device__ int    g_off[NN + 1];
__device__ int    g_cur[NN];
__device__ int    g_col[NE];
__device__ ull    g_lb[NB];                // lookback state: (state<<32)|value

__device__ __forceinline__ uint32_t smem_u32(const void* p) {
    uint32_t a;
    asm("{ .reg .u64 t; cvta.to.shared.u64 t, %1; cvt.u32.u64 %0, t; }" : "=r"(a) : "l"(p));
    return a;
}
__device__ __forceinline__ unsigned short bfu(float v) {
    return __bfloat16_as_ushort(__float2bfloat16(v));
}

// ---------------- HMMA helpers + shared GEMM tile body ----------------
__device__ __forceinline__ void mma_bf16(float* c, const uint32_t* a, uint32_t b0, uint32_t b1) {
    asm volatile(
        "mma.sync.aligned.m16n8k16.row.col.f32.bf16.bf16.f32 "
        "{%0,%1,%2,%3}, {%4,%5,%6,%7}, {%8,%9}, {%0,%1,%2,%3};"
        : "+f"(c[0]), "+f"(c[1]), "+f"(c[2]), "+f"(c[3])
        : "r"(a[0]), "r"(a[1]), "r"(a[2]), "r"(a[3]), "r"(b0), "r"(b1));
}
__device__ __forceinline__ void ldm_x4(uint32_t* a, uint32_t addr) {
    asm volatile("ldmatrix.sync.aligned.m8n8.x4.shared.b16 {%0,%1,%2,%3}, [%4];"
                 : "=r"(a[0]), "=r"(a[1]), "=r"(a[2]), "=r"(a[3]) : "r"(addr));
}

#define GSMEM (2 * 128 * ROWPAD * 2)   // A_hi + A_lo, 69632 B

__device__ __forceinline__ void gemm_tile(char* smem, int tile,
                                          const float* __restrict__ X,
                                          const float* __restrict__ W,
                                          const float* __restrict__ Bias) {
    __nv_bfloat16* Ah = (__nv_bfloat16*)smem;
    __nv_bfloat16* Al = (__nv_bfloat16*)(smem + 128 * ROWPAD * 2);

    const int tid = threadIdx.x;
    const int w = tid >> 5;
    const int lane = tid & 31;
    const int r0 = tile * 128;

    // ---- load X tile, split-convert to hi/lo bf16 in SMEM ----
#pragma unroll
    for (int it = 0; it < 16; it++) {
        int idx = tid + it * 256;          // 4096 float4
        int row = idx >> 5;
        int kq  = idx & 31;
        float4 v = make_float4(0.f, 0.f, 0.f, 0.f);
        if (r0 + row < NN) v = *(const float4*)(X + (size_t)(r0 + row) * DD + kq * 4);
        __nv_bfloat16 hx = __float2bfloat16(v.x), hy = __float2bfloat16(v.y);
        __nv_bfloat16 hz = __float2bfloat16(v.z), hw = __float2bfloat16(v.w);
        uint32_t hi01 = ((uint32_t)__bfloat16_as_ushort(hy) << 16) | __bfloat16_as_ushort(hx);
        uint32_t hi23 = ((uint32_t)__bfloat16_as_ushort(hw) << 16) | __bfloat16_as_ushort(hz);
        uint32_t lo01 = ((uint32_t)bfu(v.y - __bfloat162float(hy)) << 16) | bfu(v.x - __bfloat162float(hx));
        uint32_t lo23 = ((uint32_t)bfu(v.w - __bfloat162float(hw)) << 16) | bfu(v.z - __bfloat162float(hz));
        *(ull*)(Ah + row * ROWPAD + kq * 4) = ((ull)hi23 << 32) | hi01;
        *(ull*)(Al + row * ROWPAD + kq * 4) = ((ull)lo23 << 32) | lo01;
    }

    // ---- build resident B fragments directly from W (L2-hot, 64KB) ----
    uint32_t bh[2][8][2], bl[2][8][2];
#pragma unroll
    for (int t = 0; t < 2; t++)
#pragma unroll
        for (int ks = 0; ks < 8; ks++)
#pragma unroll
            for (int r = 0; r < 2; r++) {
                int n = w * 16 + t * 8 + (lane >> 2);
                int k = ks * 16 + r * 8 + (lane & 3) * 2;
                float2 v = *(const float2*)(W + n * DD + k);
                __nv_bfloat16 h0 = __float2bfloat16(v.x), h1 = __float2bfloat16(v.y);
                bh[t][ks][r] = ((uint32_t)__bfloat16_as_ushort(h1) << 16) | __bfloat16_as_ushort(h0);
                bl[t][ks][r] = ((uint32_t)bfu(v.y - __bfloat162float(h1)) << 16) |
                               bfu(v.x - __bfloat162float(h0));
            }

    const int t2 = lane & 3;
    const int g  = lane >> 2;
    float2 bias0 = *(const float2*)(Bias + w * 16 + t2 * 2);
    float2 bias1 = *(const float2*)(Bias + w * 16 + 8 + t2 * 2);

    __syncthreads();

    const uint32_t ah_base = smem_u32(Ah);
    const uint32_t al_base = smem_u32(Al);
    const uint32_t rowoff =
        ((((lane >> 3) & 1) * 8 + (lane & 7)) * ROWPAD + (lane >> 4) * 8) * 2;

#pragma unroll
    for (int mt = 0; mt < 8; mt++) {
        float acc0[4] = {0.f, 0.f, 0.f, 0.f};
        float acc1[4] = {0.f, 0.f, 0.f, 0.f};
#pragma unroll
        for (int ks = 0; ks < 8; ks++) {
            uint32_t off = (uint32_t)(mt * 16 * ROWPAD * 2 + ks * 32) + rowoff;
            uint32_t ah[4], al[4];
            ldm_x4(ah, ah_base + off);
            ldm_x4(al, al_base + off);
            mma_bf16(acc0, ah, bh[0][ks][0], bh[0][ks][1]);
            mma_bf16(acc1, ah, bh[1][ks][0], bh[1][ks][1]);
            mma_bf16(acc0, ah, bl[0][ks][0], bl[0][ks][1]);
            mma_bf16(acc1, ah, bl[1][ks][0], bl[1][ks][1]);
            mma_bf16(acc0, al, bh[0][ks][0], bh[0][ks][1]);
            mma_bf16(acc1, al, bh[1][ks][0], bh[1][ks][1]);
        }
        int row = r0 + mt * 16 + g;
        int col0 = w * 16 + t2 * 2;
        if (row < NN) {
            __half* q = g_hf + (size_t)row * DD;
            *(__half2*)(q + col0) =
                __float22half2_rn(make_float2(acc0[0] + bias0.x, acc0[1] + bias0.y));
            *(__half2*)(q + col0 + 8) =
                __float22half2_rn(make_float2(acc1[0] + bias1.x, acc1[1] + bias1.y));
        }
        if (row + 8 < NN) {
            __half* q = g_hf + (size_t)(row + 8) * DD;
            *(__half2*)(q + col0) =
                __float22half2_rn(make_float2(acc0[2] + bias0.x, acc0[3] + bias0.y));
            *(__half2*)(q + col0 + 8) =
                __float22half2_rn(make_float2(acc1[2] + bias1.x, acc1[3] + bias1.y));
        }
    }
}

// ---------------- launch 1: hist (interleaved with gemmA tiles 0..NTA-1) ----------------
__global__ void __launch_bounds__(256) hist_gemmA_kernel(const int* __restrict__ er,
                                                         const float* __restrict__ X,
                                                         const float* __restrict__ W,
                                                         const float* __restrict__ Bias) {
    extern __shared__ char smem[];
    const int tid = threadIdx.x;
    const int bid = blockIdx.x;
    const int total = NHB + NTA;
    int gA = (int)(((long long)bid * NTA) / total);
    int gB = (int)(((long long)(bid + 1) * NTA) / total);
    if (gB > gA) {
        gemm_tile(smem, gA, X, W, Bias);
        return;
    }
    int hbid = bid - gA;
    if (hbid == 0 && tid < NB) g_lb[tid] = 0ull;

    int base = hbid * 2048 + tid * 8;
    if (base + 7 < NE) {
        int4 a = *(const int4*)(er + base);
        int4 c = *(const int4*)(er + base + 4);
        atomicAdd(&g_deg[a.x], 1);
        atomicAdd(&g_deg[a.y], 1);
        atomicAdd(&g_deg[a.z], 1);
        atomicAdd(&g_deg[a.w], 1);
        atomicAdd(&g_deg[c.x], 1);
        atomicAdd(&g_deg[c.y], 1);
        atomicAdd(&g_deg[c.z], 1);
        atomicAdd(&g_deg[c.w], 1);
    } else {
        for (int e = base; e < NE; e++) atomicAdd(&g_deg[er[e]], 1);
    }
}

// ---------------- launch 2: scan (blocks 0..NB-1) + gemm tiles NTA..NTA+NTS-1 ----------------
__global__ void __launch_bounds__(256) scan_gemm_kernel(const float* __restrict__ X,
                                                        const float* __restrict__ W,
                                                        const float* __restrict__ Bias) {
    extern __shared__ char smem[];
    const int tid = threadIdx.x;

    if (blockIdx.x >= NB) {
        gemm_tile(smem, NTA + (blockIdx.x - NB), X, W, Bias);
        return;
    }

    __shared__ int sh[256];
    __shared__ int s_prefix;
    const int bid = blockIdx.x;
    const int base = bid * 1024 + tid * 4;

    int vals[4];
    int s = 0;
#pragma unroll
    for (int k = 0; k < 4; k++) {
        int i = base + k;
        vals[k] = (i < NN) ? g_deg[i] : 0;
        if (i < NN) g_deg[i] = 0;          // restore invariant for next replay
        s += vals[k];
    }
    sh[tid] = s;
    __syncthreads();
    for (int off = 1; off < 256; off <<= 1) {
        int t = (tid >= off) ? sh[tid - off] : 0;
        __syncthreads();
        sh[tid] += t;
        __syncthreads();
    }
    const int T = sh[255];
    const int excl_local = sh[tid] - s;

    if (tid == 0) {
        ull pub = ((bid == 0) ? (2ull << 32) : (1ull << 32)) | (unsigned)T;
        atomicExch(&g_lb[bid], pub);
        if (bid == 0) s_prefix = 0;
    }
    if (bid > 0 && tid < 32) {
        int sum = 0;
        int wb = bid;
        while (true) {
            int idx = wb - 32 + tid;
            ull v;
            unsigned st;
            while (true) {
                v = (idx >= 0) ? atomicOr(&g_lb[idx], 0ull) : (2ull << 32);
                st = (unsigned)(v >> 32);
                if (__all_sync(0xffffffffu, st != 0)) break;
            }
            unsigned pmask = __ballot_sync(0xffffffffu, st == 2);
            if (pmask) {
                int lead = 31 - __clz(pmask);
                int c = (tid >= lead) ? (int)(v & 0xffffffffu) : 0;
#pragma unroll
                for (int o = 16; o; o >>= 1) c += __shfl_down_sync(0xffffffffu, c, o);
                if (tid == 0) sum += c;
                break;
            } else {
                int c = (int)(v & 0xffffffffu);
#pragma unroll
                for (int o = 16; o; o >>= 1) c += __shfl_down_sync(0xffffffffu, c, o);
                if (tid == 0) sum += c;
                wb -= 32;
            }
        }
        if (tid == 0) {
            s_prefix = sum;
            atomicExch(&g_lb[bid], (2ull << 32) | (unsigned)(sum + T));
        }
    }
    __syncthreads();

    int excl = excl_local + s_prefix;
#pragma unroll
    for (int k = 0; k < 4; k++) {
        int i = base + k;
        if (i < NN) { g_off[i] = excl; g_cur[i] = excl; }
        excl += vals[k];
    }
    if (bid == NB - 1 && tid == 255) g_off[NN] = excl;
}

// ---------------- launch 3: permute (interleaved with gemmB tiles) ----------------
__global__ void __launch_bounds__(256) perm_gemmB_kernel(const int* __restrict__ er,
                                                         const int* __restrict__ ec,
                                                         const float* __restrict__ X,
                                                         const float* __restrict__ W,
                                                         const float* __restrict__ Bias) {
    extern __shared__ char smem[];
    const int tid = threadIdx.x;
    const int bid = blockIdx.x;
    const int total = NPERM + NTB;
    int gA = (int)(((long long)bid * NTB) / total);
    int gB = (int)(((long long)(bid + 1) * NTB) / total);
    if (gB > gA) {
        gemm_tile(smem, NTA + NTS + gA, X, W, Bias);
        return;
    }
    int pbid = bid - gA;

    int base = pbid * 2048 + tid * 8;
    if (base + 7 < NE) {
        int4 r0 = *(const int4*)(er + base);
        int4 r1 = *(const int4*)(er + base + 4);
        int4 c0 = *(const int4*)(ec + base);
        int4 c1 = *(const int4*)(ec + base + 4);
        int p0 = atomicAdd(&g_cur[r0.x], 1);
        int p1 = atomicAdd(&g_cur[r0.y], 1);
        int p2 = atomicAdd(&g_cur[r0.z], 1);
        int p3 = atomicAdd(&g_cur[r0.w], 1);
        int p4 = atomicAdd(&g_cur[r1.x], 1);
        int p5 = atomicAdd(&g_cur[r1.y], 1);
        int p6 = atomicAdd(&g_cur[r1.z], 1);
        int p7 = atomicAdd(&g_cur[r1.w], 1);
        g_col[p0] = c0.x; g_col[p1] = c0.y; g_col[p2] = c0.z; g_col[p3] = c0.w;
        g_col[p4] = c1.x; g_col[p5] = c1.y; g_col[p6] = c1.z; g_col[p7] = c1.w;
    } else {
        for (int e = base; e < NE; e++) {
            int pos = atomicAdd(&g_cur[er[e]], 1);
            g_col[pos] = ec[e];
        }
    }
}

// ---------------- launch 4: gather — int4 col loads + 8-deep fp16 tree ----------------
__global__ void __launch_bounds__(256) gather_kernel(float* __restrict__ out) {
    int warp = (blockIdx.x * 256 + threadIdx.x) >> 5;
    int lane = threadIdx.x & 31;
    if (warp >= NN) return;
    int beg = g_off[warp];
    int end = g_off[warp + 1];

    const __half* hb = g_hf + lane * 4;

    // self-loop, flushed to fp32 immediately
    uint2 sv = *(const uint2*)(hb + (size_t)warp * DD);
    float2 sf0 = __half22float2(*(__half2*)&sv.x);
    float2 sf1 = __half22float2(*(__half2*)&sv.y);
    float4 acc = make_float4(sf0.x, sf0.y, sf1.x, sf1.y);

    int e = beg;
    // align to 4 for int4 column loads
    for (; e < end && (e & 3); e++) {
        uint2 v = *(const uint2*)(hb + (size_t)g_col[e] * DD);
        float2 f0 = __half22float2(*(__half2*)&v.x);
        float2 f1 = __half22float2(*(__half2*)&v.y);
        acc.x += f0.x; acc.y += f0.y; acc.z += f1.x; acc.w += f1.y;
    }
    // 8 edges per iteration: 2 int4 col loads, 8 row loads, one depth-3 fp16 tree
    for (; e + 8 <= end; e += 8) {
        int4 ca = *(const int4*)(g_col + e);
        int4 cb = *(const int4*)(g_col + e + 4);
        uint2 v0 = *(const uint2*)(hb + (size_t)ca.x * DD);
        uint2 v1 = *(const uint2*)(hb + (size_t)ca.y * DD);
        uint2 v2 = *(const uint2*)(hb + (size_t)ca.z * DD);
        uint2 v3 = *(const uint2*)(hb + (size_t)ca.w * DD);
        uint2 v4 = *(const uint2*)(hb + (size_t)cb.x * DD);
        uint2 v5 = *(const uint2*)(hb + (size_t)cb.y * DD);
        uint2 v6 = *(const uint2*)(hb + (size_t)cb.z * DD);
        uint2 v7 = *(const uint2*)(hb + (size_t)cb.w * DD);
        __half2 a0 = __hadd2(*(__half2*)&v0.x, *(__half2*)&v1.x);
        __half2 a1 = __hadd2(*(__half2*)&v2.x, *(__half2*)&v3.x);
        __half2 a2 = __hadd2(*(__half2*)&v4.x, *(__half2*)&v5.x);
        __half2 a3 = __hadd2(*(__half2*)&v6.x, *(__half2*)&v7.x);
        __half2 b0 = __hadd2(*(__half2*)&v0.y, *(__half2*)&v1.y);
        __half2 b1 = __hadd2(*(__half2*)&v2.y, *(__half2*)&v3.y);
        __half2 b2 = __hadd2(*(__half2*)&v4.y, *(__half2*)&v5.y);
        __half2 b3 = __hadd2(*(__half2*)&v6.y, *(__half2*)&v7.y);
        __half2 u0 = __hadd2(__hadd2(a0, a1), __hadd2(a2, a3));
        __half2 u1 = __hadd2(__hadd2(b0, b1), __hadd2(b2, b3));
        float2 f0 = __half22float2(u0);
        float2 f1 = __half22float2(u1);
        acc.x += f0.x; acc.y += f0.y; acc.z += f1.x; acc.w += f1.y;
    }
    // 4-edge tail
    for (; e + 4 <= end; e += 4) {
        int4 ca = *(const int4*)(g_col + e);
        uint2 v0 = *(const uint2*)(hb + (size_t)ca.x * DD);
        uint2 v1 = *(const uint2*)(hb + (size_t)ca.y * DD);
        uint2 v2 = *(const uint2*)(hb + (size_t)ca.z * DD);
        uint2 v3 = *(const uint2*)(hb + (size_t)ca.w * DD);
        __half2 u0 = __hadd2(__hadd2(*(__half2*)&v0.x, *(__half2*)&v1.x),
                             __hadd2(*(__half2*)&v2.x, *(__half2*)&v3.x));
        __half2 u1 = __hadd2(__hadd2(*(__half2*)&v0.y, *(__half2*)&v1.y),
                             __hadd2(*(__half2*)&v2.y, *(__half2*)&v3.y));
        float2 f0 = __half22float2(u0);
        float2 f1 = __half22float2(u1);
        acc.x += f0.x; acc.y += f0.y; acc.z += f1.x; acc.w += f1.y;
    }
    for (; e < end; e++) {
        uint2 v = *(const uint2*)(hb + (size_t)g_col[e] * DD);
        float2 f0 = __half22float2(*(__half2*)&v.x);
        float2 f1 = __half22float2(*(__half2*)&v.y);
        acc.x += f0.x; acc.y += f0.y; acc.z += f1.x; acc.w += f1.y;
    }

    float inv = 1.0f / (float)(end - beg + 1);
    acc.x = fmaxf(acc.x * inv, 0.f);
    acc.y = fmaxf(acc.y * inv, 0.f);
    acc.z = fmaxf(acc.z * inv, 0.f);
    acc.w = fmaxf(acc.w * inv, 0.f);
    *(float4*)(out + (size_t)warp * DD + lane * 4) = acc;
}

extern "C" void kernel_launch(void* const* d_in, const int* in_sizes, int n_in,
                              void* d_out, int out_size) {
    const float* x  = (const float*)d_in[0];
    const float* W  = (const float*)d_in[1];
    const float* b  = (const float*)d_in[2];
    const int* er   = (const int*)d_in[3];
    const int* ec   = (const int*)d_in[4];
    float* out      = (float*)d_out;

    cudaFuncSetAttribute(hist_gemmA_kernel, cudaFuncAttributeMaxDynamicSharedMemorySize, GSMEM);
    hist_gemmA_kernel<<<NHB + NTA, 256, GSMEM>>>(er, x, W, b);

    cudaFuncSetAttribute(scan_gemm_kernel, cudaFuncAttributeMaxDynamicSharedMemorySize, GSMEM);
    scan_gemm_kernel<<<NB + NTS, 256, GSMEM>>>(x, W, b);

    cudaFuncSetAttribute(perm_gemmB_kernel, cudaFuncAttributeMaxDynamicSharedMemorySize, GSMEM);
    perm_gemmB_kernel<<<NPERM + NTB, 256, GSMEM>>>(er, ec, x, W, b);

    gather_kernel<<<(NN * 32 + 255) / 256, 256>>>(out);
}

// round 11
// speedup vs baseline: 1.0576x; 1.0576x over previous
#include <cuda_runtime.h>
#include <cuda_bf16.h>
#include <cuda_fp16.h>
#include <cstdint>

#define NN 100000
#define NE 1600000
#define DD 128
#define NB ((NN + 1023) / 1024)       // 98 scan blocks
#define NTILE ((NN + 127) / 128)      // 782 GEMM tiles
#define NT2 191                       // gemm tiles in launch 2 (with scan)
#define NT3 (NTILE - NT2)             // 591 gemm tiles in launch 3 (with permute)
#define NHB ((NE + 2047) / 2048)      // 782 hist blocks (ILP8)
#define NPERM ((NE + 2047) / 2048)    // 782 permute blocks (ILP8)
#define ROWPAD 136                    // bf16 elems per SMEM row (272B, conflict-free)

typedef unsigned long long ull;

// ---------------- scratch (__device__ globals; zero-initialized at load) ----------------
__device__ __half g_hf[(size_t)NN * DD];   // 25.6 MB fp16 h = x @ W.T + b
__device__ int    g_deg[NN];               // invariant: 0 at kernel_launch entry
__device__ int    g_off[NN + 1];
__device__ int    g_cur[NN];
__device__ int    g_col[NE];               // holds BYTE offsets (col * 256)
__device__ ull    g_lb[NB];                // lookback state: (state<<32)|value

__device__ __forceinline__ uint32_t smem_u32(const void* p) {
    uint32_t a;
    asm("{ .reg .u64 t; cvta.to.shared.u64 t, %1; cvt.u32.u64 %0, t; }" : "=r"(a) : "l"(p));
    return a;
}
__device__ __forceinline__ unsigned short bfu(float v) {
    return __bfloat16_as_ushort(__float2bfloat16(v));
}

// ---------------- HMMA helpers + shared GEMM tile body ----------------
__device__ __forceinline__ void mma_bf16(float* c, const uint32_t* a, uint32_t b0, uint32_t b1) {
    asm volatile(
        "mma.sync.aligned.m16n8k16.row.col.f32.bf16.bf16.f32 "
        "{%0,%1,%2,%3}, {%4,%5,%6,%7}, {%8,%9}, {%0,%1,%2,%3};"
        : "+f"(c[0]), "+f"(c[1]), "+f"(c[2]), "+f"(c[3])
        : "r"(a[0]), "r"(a[1]), "r"(a[2]), "r"(a[3]), "r"(b0), "r"(b1));
}
__device__ __forceinline__ void ldm_x4(uint32_t* a, uint32_t addr) {
    asm volatile("ldmatrix.sync.aligned.m8n8.x4.shared.b16 {%0,%1,%2,%3}, [%4];"
                 : "=r"(a[0]), "=r"(a[1]), "=r"(a[2]), "=r"(a[3]) : "r"(addr));
}

#define GSMEM (2 * 128 * ROWPAD * 2)   // A_hi + A_lo, 69632 B

__device__ __forceinline__ void gemm_tile(char* smem, int tile,
                                          const float* __restrict__ X,
                                          const float* __restrict__ W,
                                          const float* __restrict__ Bias) {
    __nv_bfloat16* Ah = (__nv_bfloat16*)smem;
    __nv_bfloat16* Al = (__nv_bfloat16*)(smem + 128 * ROWPAD * 2);

    const int tid = threadIdx.x;
    const int w = tid >> 5;
    const int lane = tid & 31;
    const int r0 = tile * 128;

    // ---- load X tile, split-convert to hi/lo bf16 in SMEM ----
#pragma unroll
    for (int it = 0; it < 16; it++) {
        int idx = tid + it * 256;          // 4096 float4
        int row = idx >> 5;
        int kq  = idx & 31;
        float4 v = make_float4(0.f, 0.f, 0.f, 0.f);
        if (r0 + row < NN) v = *(const float4*)(X + (size_t)(r0 + row) * DD + kq * 4);
        __nv_bfloat16 hx = __float2bfloat16(v.x), hy = __float2bfloat16(v.y);
        __nv_bfloat16 hz = __float2bfloat16(v.z), hw = __float2bfloat16(v.w);
        uint32_t hi01 = ((uint32_t)__bfloat16_as_ushort(hy) << 16) | __bfloat16_as_ushort(hx);
        uint32_t hi23 = ((uint32_t)__bfloat16_as_ushort(hw) << 16) | __bfloat16_as_ushort(hz);
        uint32_t lo01 = ((uint32_t)bfu(v.y - __bfloat162float(hy)) << 16) | bfu(v.x - __bfloat162float(hx));
        uint32_t lo23 = ((uint32_t)bfu(v.w - __bfloat162float(hw)) << 16) | bfu(v.z - __bfloat162float(hz));
        *(ull*)(Ah + row * ROWPAD + kq * 4) = ((ull)hi23 << 32) | hi01;
        *(ull*)(Al + row * ROWPAD + kq * 4) = ((ull)lo23 << 32) | lo01;
    }

    // ---- build resident B fragments directly from W (L2-hot, 64KB) ----
    uint32_t bh[2][8][2], bl[2][8][2];
#pragma unroll
    for (int t = 0; t < 2; t++)
#pragma unroll
        for (int ks = 0; ks < 8; ks++)
#pragma unroll
            for (int r = 0; r < 2; r++) {
                int n = w * 16 + t * 8 + (lane >> 2);
                int k = ks * 16 + r * 8 + (lane & 3) * 2;
                float2 v = *(const float2*)(W + n * DD + k);
                __nv_bfloat16 h0 = __float2bfloat16(v.x), h1 = __float2bfloat16(v.y);
                bh[t][ks][r] = ((uint32_t)__bfloat16_as_ushort(h1) << 16) | __bfloat16_as_ushort(h0);
                bl[t][ks][r] = ((uint32_t)bfu(v.y - __bfloat162float(h1)) << 16) |
                               bfu(v.x - __bfloat162float(h0));
            }

    const int t2 = lane & 3;
    const int g  = lane >> 2;
    float2 bias0 = *(const float2*)(Bias + w * 16 + t2 * 2);
    float2 bias1 = *(const float2*)(Bias + w * 16 + 8 + t2 * 2);

    __syncthreads();

    const uint32_t ah_base = smem_u32(Ah);
    const uint32_t al_base = smem_u32(Al);
    const uint32_t rowoff =
        ((((lane >> 3) & 1) * 8 + (lane & 7)) * ROWPAD + (lane >> 4) * 8) * 2;

#pragma unroll
    for (int mt = 0; mt < 8; mt++) {
        float acc0[4] = {0.f, 0.f, 0.f, 0.f};
        float acc1[4] = {0.f, 0.f, 0.f, 0.f};
#pragma unroll
        for (int ks = 0; ks < 8; ks++) {
            uint32_t off = (uint32_t)(mt * 16 * ROWPAD * 2 + ks * 32) + rowoff;
            uint32_t ah[4], al[4];
            ldm_x4(ah, ah_base + off);
            ldm_x4(al, al_base + off);
            mma_bf16(acc0, ah, bh[0][ks][0], bh[0][ks][1]);
            mma_bf16(acc1, ah, bh[1][ks][0], bh[1][ks][1]);
            mma_bf16(acc0, ah, bl[0][ks][0], bl[0][ks][1]);
            mma_bf16(acc1, ah, bl[1][ks][0], bl[1][ks][1]);
            mma_bf16(acc0, al, bh[0][ks][0], bh[0][ks][1]);
            mma_bf16(acc1, al, bh[1][ks][0], bh[1][ks][1]);
        }
        int row = r0 + mt * 16 + g;
        int col0 = w * 16 + t2 * 2;
        if (row < NN) {
            __half* q = g_hf + (size_t)row * DD;
            *(__half2*)(q + col0) =
                __float22half2_rn(make_float2(acc0[0] + bias0.x, acc0[1] + bias0.y));
            *(__half2*)(q + col0 + 8) =
                __float22half2_rn(make_float2(acc1[0] + bias1.x, acc1[1] + bias1.y));
        }
        if (row + 8 < NN) {
            __half* q = g_hf + (size_t)(row + 8) * DD;
            *(__half2*)(q + col0) =
                __float22half2_rn(make_float2(acc0[2] + bias0.x, acc0[3] + bias0.y));
            *(__half2*)(q + col0 + 8) =
                __float22half2_rn(make_float2(acc1[2] + bias1.x, acc1[3] + bias1.y));
        }
    }
}

// ---------------- launch 1: histogram (pure, ILP8) + lb zero ----------------
__global__ void __launch_bounds__(256) hist_kernel(const int* __restrict__ er) {
    const int tid = threadIdx.x;
    if (blockIdx.x == 0 && tid < NB) g_lb[tid] = 0ull;

    int base = blockIdx.x * 2048 + tid * 8;
    if (base + 7 < NE) {
        int4 a = *(const int4*)(er + base);
        int4 c = *(const int4*)(er + base + 4);
        atomicAdd(&g_deg[a.x], 1);
        atomicAdd(&g_deg[a.y], 1);
        atomicAdd(&g_deg[a.z], 1);
        atomicAdd(&g_deg[a.w], 1);
        atomicAdd(&g_deg[c.x], 1);
        atomicAdd(&g_deg[c.y], 1);
        atomicAdd(&g_deg[c.z], 1);
        atomicAdd(&g_deg[c.w], 1);
    } else {
        for (int e = base; e < NE; e++) atomicAdd(&g_deg[er[e]], 1);
    }
}

// ---------------- launch 2: scan (blocks 0..NB-1) + gemm tiles 0..NT2-1 ----------------
__global__ void __launch_bounds__(256) scan_gemm_kernel(const float* __restrict__ X,
                                                        const float* __restrict__ W,
                                                        const float* __restrict__ Bias) {
    extern __shared__ char smem[];
    const int tid = threadIdx.x;

    if (blockIdx.x >= NB) {
        gemm_tile(smem, blockIdx.x - NB, X, W, Bias);
        return;
    }

    __shared__ int sh[256];
    __shared__ int s_prefix;
    const int bid = blockIdx.x;
    const int base = bid * 1024 + tid * 4;

    int vals[4];
    int s = 0;
#pragma unroll
    for (int k = 0; k < 4; k++) {
        int i = base + k;
        vals[k] = (i < NN) ? g_deg[i] : 0;
        if (i < NN) g_deg[i] = 0;          // restore invariant for next replay
        s += vals[k];
    }
    sh[tid] = s;
    __syncthreads();
    for (int off = 1; off < 256; off <<= 1) {
        int t = (tid >= off) ? sh[tid - off] : 0;
        __syncthreads();
        sh[tid] += t;
        __syncthreads();
    }
    const int T = sh[255];
    const int excl_local = sh[tid] - s;

    if (tid == 0) {
        ull pub = ((bid == 0) ? (2ull << 32) : (1ull << 32)) | (unsigned)T;
        atomicExch(&g_lb[bid], pub);
        if (bid == 0) s_prefix = 0;
    }
    if (bid > 0 && tid < 32) {
        int sum = 0;
        int wb = bid;
        while (true) {
            int idx = wb - 32 + tid;
            ull v;
            unsigned st;
            while (true) {
                v = (idx >= 0) ? atomicOr(&g_lb[idx], 0ull) : (2ull << 32);
                st = (unsigned)(v >> 32);
                if (__all_sync(0xffffffffu, st != 0)) break;
            }
            unsigned pmask = __ballot_sync(0xffffffffu, st == 2);
            if (pmask) {
                int lead = 31 - __clz(pmask);
                int c = (tid >= lead) ? (int)(v & 0xffffffffu) : 0;
#pragma unroll
                for (int o = 16; o; o >>= 1) c += __shfl_down_sync(0xffffffffu, c, o);
                if (tid == 0) sum += c;
                break;
            } else {
                int c = (int)(v & 0xffffffffu);
#pragma unroll
                for (int o = 16; o; o >>= 1) c += __shfl_down_sync(0xffffffffu, c, o);
                if (tid == 0) sum += c;
                wb -= 32;
            }
        }
        if (tid == 0) {
            s_prefix = sum;
            atomicExch(&g_lb[bid], (2ull << 32) | (unsigned)(sum + T));
        }
    }
    __syncthreads();

    int excl = excl_local + s_prefix;
#pragma unroll
    for (int k = 0; k < 4; k++) {
        int i = base + k;
        if (i < NN) { g_off[i] = excl; g_cur[i] = excl; }
        excl += vals[k];
    }
    if (bid == NB - 1 && tid == 255) g_off[NN] = excl;
}

// ---------------- launch 3: permute (interleaved with gemm tiles NT2..NTILE-1) ----------------
// stores PRE-SCALED byte offsets (col * 256) into g_col
__global__ void __launch_bounds__(256) perm_gemm_kernel(const int* __restrict__ er,
                                                        const int* __restrict__ ec,
                                                        const float* __restrict__ X,
                                                        const float* __restrict__ W,
                                                        const float* __restrict__ Bias) {
    extern __shared__ char smem[];
    const int tid = threadIdx.x;
    const int bid = blockIdx.x;
    const int total = NPERM + NT3;
    int gA = (int)(((long long)bid * NT3) / total);
    int gB = (int)(((long long)(bid + 1) * NT3) / total);
    if (gB > gA) {
        gemm_tile(smem, NT2 + gA, X, W, Bias);
        return;
    }
    int pbid = bid - gA;

    int base = pbid * 2048 + tid * 8;
    if (base + 7 < NE) {
        int4 r0 = *(const int4*)(er + base);
        int4 r1 = *(const int4*)(er + base + 4);
        int4 c0 = *(const int4*)(ec + base);
        int4 c1 = *(const int4*)(ec + base + 4);
        int p0 = atomicAdd(&g_cur[r0.x], 1);
        int p1 = atomicAdd(&g_cur[r0.y], 1);
        int p2 = atomicAdd(&g_cur[r0.z], 1);
        int p3 = atomicAdd(&g_cur[r0.w], 1);
        int p4 = atomicAdd(&g_cur[r1.x], 1);
        int p5 = atomicAdd(&g_cur[r1.y], 1);
        int p6 = atomicAdd(&g_cur[r1.z], 1);
        int p7 = atomicAdd(&g_cur[r1.w], 1);
        g_col[p0] = c0.x << 8; g_col[p1] = c0.y << 8;
        g_col[p2] = c0.z << 8; g_col[p3] = c0.w << 8;
        g_col[p4] = c1.x << 8; g_col[p5] = c1.y << 8;
        g_col[p6] = c1.z << 8; g_col[p7] = c1.w << 8;
    } else {
        for (int e = base; e < NE; e++) {
            int pos = atomicAdd(&g_cur[er[e]], 1);
            g_col[pos] = ec[e] << 8;
        }
    }
}

// ---------------- launch 4: gather — 8-edge unroll, two quad trees, byte offsets ----------------
__device__ __forceinline__ void quad_acc(float4& acc, uint2 v0, uint2 v1, uint2 v2, uint2 v3) {
    __half2 s0 = __hadd2(*(__half2*)&v0.x, *(__half2*)&v1.x);
    __half2 s1 = __hadd2(*(__half2*)&v0.y, *(__half2*)&v1.y);
    __half2 t0 = __hadd2(*(__half2*)&v2.x, *(__half2*)&v3.x);
    __half2 t1 = __hadd2(*(__half2*)&v2.y, *(__half2*)&v3.y);
    __half2 u0 = __hadd2(s0, t0);
    __half2 u1 = __hadd2(s1, t1);
    float2 f0 = __half22float2(u0);
    float2 f1 = __half22float2(u1);
    acc.x += f0.x; acc.y += f0.y; acc.z += f1.x; acc.w += f1.y;
}

__global__ void __launch_bounds__(256) gather_kernel(float* __restrict__ out) {
    int warp = (blockIdx.x * 256 + threadIdx.x) >> 5;
    int lane = threadIdx.x & 31;
    if (warp >= NN) return;
    int beg = g_off[warp];
    int end = g_off[warp + 1];

    const char* hb = (const char*)g_hf + lane * 8;   // lane's 8-byte slice within each 256B row

    // self-loop, flushed to fp32
    uint2 sv = *(const uint2*)(hb + (size_t)warp * 256);
    float2 sf0 = __half22float2(*(__half2*)&sv.x);
    float2 sf1 = __half22float2(*(__half2*)&sv.y);
    float4 acc = make_float4(sf0.x, sf0.y, sf1.x, sf1.y);

    int e = beg;
    for (; e + 8 <= end; e += 8) {
        int o0 = g_col[e + 0], o1 = g_col[e + 1], o2 = g_col[e + 2], o3 = g_col[e + 3];
        int o4 = g_col[e + 4], o5 = g_col[e + 5], o6 = g_col[e + 6], o7 = g_col[e + 7];
        uint2 v0 = *(const uint2*)(hb + o0);
        uint2 v1 = *(const uint2*)(hb + o1);
        uint2 v2 = *(const uint2*)(hb + o2);
        uint2 v3 = *(const uint2*)(hb + o3);
        uint2 v4 = *(const uint2*)(hb + o4);
        uint2 v5 = *(const uint2*)(hb + o5);
        uint2 v6 = *(const uint2*)(hb + o6);
        uint2 v7 = *(const uint2*)(hb + o7);
        quad_acc(acc, v0, v1, v2, v3);
        quad_acc(acc, v4, v5, v6, v7);
    }
    for (; e + 4 <= end; e += 4) {
        int o0 = g_col[e + 0], o1 = g_col[e + 1], o2 = g_col[e + 2], o3 = g_col[e + 3];
        uint2 v0 = *(const uint2*)(hb + o0);
        uint2 v1 = *(const uint2*)(hb + o1);
        uint2 v2 = *(const uint2*)(hb + o2);
        uint2 v3 = *(const uint2*)(hb + o3);
        quad_acc(acc, v0, v1, v2, v3);
    }
    for (; e < end; e++) {
        uint2 v = *(const uint2*)(hb + g_col[e]);
        float2 f0 = __half22float2(*(__half2*)&v.x);
        float2 f1 = __half22float2(*(__half2*)&v.y);
        acc.x += f0.x; acc.y += f0.y; acc.z += f1.x; acc.w += f1.y;
    }

    float inv = 1.0f / (float)(end - beg + 1);
    acc.x = fmaxf(acc.x * inv, 0.f);
    acc.y = fmaxf(acc.y * inv, 0.f);
    acc.z = fmaxf(acc.z * inv, 0.f);
    acc.w = fmaxf(acc.w * inv, 0.f);
    *(float4*)(out + (size_t)warp * DD + lane * 4) = acc;
}

extern "C" void kernel_launch(void* const* d_in, const int* in_sizes, int n_in,
                              void* d_out, int out_size) {
    const float* x  = (const float*)d_in[0];
    const float* W  = (const float*)d_in[1];
    const float* b  = (const float*)d_in[2];
    const int* er   = (const int*)d_in[3];
    const int* ec   = (const int*)d_in[4];
    float* out      = (float*)d_out;

    hist_kernel<<<NHB, 256>>>(er);

    cudaFuncSetAttribute(scan_gemm_kernel, cudaFuncAttributeMaxDynamicSharedMemorySize, GSMEM);
    scan_gemm_kernel<<<NB + NT2, 256, GSMEM>>>(x, W, b);

    cudaFuncSetAttribute(perm_gemm_kernel, cudaFuncAttributeMaxDynamicSharedMemorySize, GSMEM);
    perm_gemm_kernel<<<NPERM + NT3, 256, GSMEM>>>(er, ec, x, W, b);

    gather_kernel<<<(NN * 32 + 255) / 256, 256>>>(out);
}

// round 12
// speedup vs baseline: 1.0585x; 1.0009x over previous
#include <cuda_runtime.h>
#include <cuda_bf16.h>
#include <cuda_fp16.h>
#include <cstdint>

#define NN 100000
#define NE 1600000
#define DD 128
#define NB ((NN + 1023) / 1024)       // 98 scan blocks
#define NTILE ((NN + 127) / 128)      // 782 GEMM tiles
#define NT2 134                       // gemm tiles in launch 2 (with scan)
#define NT3 (NTILE - NT2)             // 648 gemm tiles in launch 3 (with permute)
#define NHB ((NE + 2047) / 2048)      // 782 hist blocks (ILP8)
#define NPERM ((NE + 2047) / 2048)    // 782 permute blocks (ILP8)
#define ROWPAD 136                    // fp16 elems per SMEM row (272B, conflict-free)

typedef unsigned long long ull;

// ---------------- scratch (__device__ globals; zero-initialized at load) ----------------
__device__ __half g_hf[(size_t)NN * DD];   // 25.6 MB fp16 h = x @ W.T + b
__device__ int    g_deg[NN];               // invariant: 0 at kernel_launch entry
__device__ int    g_off[NN + 1];
__device__ int    g_cur[NN];
__device__ int    g_col[NE];
__device__ ull    g_lb[NB];                // lookback state: (state<<32)|value

__device__ __forceinline__ uint32_t smem_u32(const void* p) {
    uint32_t a;
    asm("{ .reg .u64 t; cvta.to.shared.u64 t, %1; cvt.u32.u64 %0, t; }" : "=r"(a) : "l"(p));
    return a;
}

// ---------------- HMMA helpers + shared GEMM tile body (fp16 single-term) ----------------
__device__ __forceinline__ void mma_f16(float* c, const uint32_t* a, uint32_t b0, uint32_t b1) {
    asm volatile(
        "mma.sync.aligned.m16n8k16.row.col.f32.f16.f16.f32 "
        "{%0,%1,%2,%3}, {%4,%5,%6,%7}, {%8,%9}, {%0,%1,%2,%3};"
        : "+f"(c[0]), "+f"(c[1]), "+f"(c[2]), "+f"(c[3])
        : "r"(a[0]), "r"(a[1]), "r"(a[2]), "r"(a[3]), "r"(b0), "r"(b1));
}
__device__ __forceinline__ void ldm_x4(uint32_t* a, uint32_t addr) {
    asm volatile("ldmatrix.sync.aligned.m8n8.x4.shared.b16 {%0,%1,%2,%3}, [%4];"
                 : "=r"(a[0]), "=r"(a[1]), "=r"(a[2]), "=r"(a[3]) : "r"(addr));
}

#define GSMEM (128 * ROWPAD * 2)   // single fp16 A buffer, 34816 B -> 6 blocks/SM

__device__ __forceinline__ void gemm_tile(char* smem, int tile,
                                          const float* __restrict__ X,
                                          const float* __restrict__ W,
                                          const float* __restrict__ Bias) {
    __half* Ah = (__half*)smem;

    const int tid = threadIdx.x;
    const int w = tid >> 5;
    const int lane = tid & 31;
    const int r0 = tile * 128;

    // ---- load X tile, convert to fp16 in SMEM ----
#pragma unroll
    for (int it = 0; it < 16; it++) {
        int idx = tid + it * 256;          // 4096 float4
        int row = idx >> 5;
        int kq  = idx & 31;
        float4 v = make_float4(0.f, 0.f, 0.f, 0.f);
        if (r0 + row < NN) v = *(const float4*)(X + (size_t)(r0 + row) * DD + kq * 4);
        __half2 h01 = __float22half2_rn(make_float2(v.x, v.y));
        __half2 h23 = __float22half2_rn(make_float2(v.z, v.w));
        uint32_t u01 = *(uint32_t*)&h01;
        uint32_t u23 = *(uint32_t*)&h23;
        *(ull*)(Ah + row * ROWPAD + kq * 4) = ((ull)u23 << 32) | u01;
    }

    // ---- build resident fp16 B fragments directly from W (L2-hot, 64KB) ----
    uint32_t bh[2][8][2];
#pragma unroll
    for (int t = 0; t < 2; t++)
#pragma unroll
        for (int ks = 0; ks < 8; ks++)
#pragma unroll
            for (int r = 0; r < 2; r++) {
                int n = w * 16 + t * 8 + (lane >> 2);
                int k = ks * 16 + r * 8 + (lane & 3) * 2;
                float2 v = *(const float2*)(W + n * DD + k);
                __half2 h = __float22half2_rn(v);
                bh[t][ks][r] = *(uint32_t*)&h;
            }

    const int t2 = lane & 3;
    const int g  = lane >> 2;
    float2 bias0 = *(const float2*)(Bias + w * 16 + t2 * 2);
    float2 bias1 = *(const float2*)(Bias + w * 16 + 8 + t2 * 2);

    __syncthreads();

    const uint32_t ah_base = smem_u32(Ah);
    const uint32_t rowoff =
        ((((lane >> 3) & 1) * 8 + (lane & 7)) * ROWPAD + (lane >> 4) * 8) * 2;

#pragma unroll
    for (int mt = 0; mt < 8; mt++) {
        float acc0[4] = {0.f, 0.f, 0.f, 0.f};
        float acc1[4] = {0.f, 0.f, 0.f, 0.f};
#pragma unroll
        for (int ks = 0; ks < 8; ks++) {
            uint32_t off = (uint32_t)(mt * 16 * ROWPAD * 2 + ks * 32) + rowoff;
            uint32_t ah[4];
            ldm_x4(ah, ah_base + off);
            mma_f16(acc0, ah, bh[0][ks][0], bh[0][ks][1]);
            mma_f16(acc1, ah, bh[1][ks][0], bh[1][ks][1]);
        }
        int row = r0 + mt * 16 + g;
        int col0 = w * 16 + t2 * 2;
        if (row < NN) {
            __half* q = g_hf + (size_t)row * DD;
            *(__half2*)(q + col0) =
                __float22half2_rn(make_float2(acc0[0] + bias0.x, acc0[1] + bias0.y));
            *(__half2*)(q + col0 + 8) =
                __float22half2_rn(make_float2(acc1[0] + bias1.x, acc1[1] + bias1.y));
        }
        if (row + 8 < NN) {
            __half* q = g_hf + (size_t)(row + 8) * DD;
            *(__half2*)(q + col0) =
                __float22half2_rn(make_float2(acc0[2] + bias0.x, acc0[3] + bias0.y));
            *(__half2*)(q + col0 + 8) =
                __float22half2_rn(make_float2(acc1[2] + bias1.x, acc1[3] + bias1.y));
        }
    }
}

// ---------------- launch 1: histogram (pure, ILP8) + lb zero ----------------
__global__ void __launch_bounds__(256) hist_kernel(const int* __restrict__ er) {
    const int tid = threadIdx.x;
    if (blockIdx.x == 0 && tid < NB) g_lb[tid] = 0ull;

    int base = blockIdx.x * 2048 + tid * 8;
    if (base + 7 < NE) {
        int4 a = *(const int4*)(er + base);
        int4 c = *(const int4*)(er + base + 4);
        atomicAdd(&g_deg[a.x], 1);
        atomicAdd(&g_deg[a.y], 1);
        atomicAdd(&g_deg[a.z], 1);
        atomicAdd(&g_deg[a.w], 1);
        atomicAdd(&g_deg[c.x], 1);
        atomicAdd(&g_deg[c.y], 1);
        atomicAdd(&g_deg[c.z], 1);
        atomicAdd(&g_deg[c.w], 1);
    } else {
        for (int e = base; e < NE; e++) atomicAdd(&g_deg[er[e]], 1);
    }
}

// ---------------- launch 2: scan (blocks 0..NB-1) + gemm tiles 0..NT2-1 ----------------
__global__ void __launch_bounds__(256) scan_gemm_kernel(const float* __restrict__ X,
                                                        const float* __restrict__ W,
                                                        const float* __restrict__ Bias) {
    extern __shared__ char smem[];
    const int tid = threadIdx.x;

    if (blockIdx.x >= NB) {
        gemm_tile(smem, blockIdx.x - NB, X, W, Bias);
        return;
    }

    __shared__ int sh[256];
    __shared__ int s_prefix;
    const int bid = blockIdx.x;
    const int base = bid * 1024 + tid * 4;

    int vals[4];
    int s = 0;
#pragma unroll
    for (int k = 0; k < 4; k++) {
        int i = base + k;
        vals[k] = (i < NN) ? g_deg[i] : 0;
        if (i < NN) g_deg[i] = 0;          // restore invariant for next replay
        s += vals[k];
    }
    sh[tid] = s;
    __syncthreads();
    for (int off = 1; off < 256; off <<= 1) {
        int t = (tid >= off) ? sh[tid - off] : 0;
        __syncthreads();
        sh[tid] += t;
        __syncthreads();
    }
    const int T = sh[255];
    const int excl_local = sh[tid] - s;

    if (tid == 0) {
        ull pub = ((bid == 0) ? (2ull << 32) : (1ull << 32)) | (unsigned)T;
        atomicExch(&g_lb[bid], pub);
        if (bid == 0) s_prefix = 0;
    }
    if (bid > 0 && tid < 32) {
        int sum = 0;
        int wb = bid;
        while (true) {
            int idx = wb - 32 + tid;
            ull v;
            unsigned st;
            while (true) {
                v = (idx >= 0) ? atomicOr(&g_lb[idx], 0ull) : (2ull << 32);
                st = (unsigned)(v >> 32);
                if (__all_sync(0xffffffffu, st != 0)) break;
            }
            unsigned pmask = __ballot_sync(0xffffffffu, st == 2);
            if (pmask) {
                int lead = 31 - __clz(pmask);
                int c = (tid >= lead) ? (int)(v & 0xffffffffu) : 0;
#pragma unroll
                for (int o = 16; o; o >>= 1) c += __shfl_down_sync(0xffffffffu, c, o);
                if (tid == 0) sum += c;
                break;
            } else {
                int c = (int)(v & 0xffffffffu);
#pragma unroll
                for (int o = 16; o; o >>= 1) c += __shfl_down_sync(0xffffffffu, c, o);
                if (tid == 0) sum += c;
                wb -= 32;
            }
        }
        if (tid == 0) {
            s_prefix = sum;
            atomicExch(&g_lb[bid], (2ull << 32) | (unsigned)(sum + T));
        }
    }
    __syncthreads();

    int excl = excl_local + s_prefix;
#pragma unroll
    for (int k = 0; k < 4; k++) {
        int i = base + k;
        if (i < NN) { g_off[i] = excl; g_cur[i] = excl; }
        excl += vals[k];
    }
    if (bid == NB - 1 && tid == 255) g_off[NN] = excl;
}

// ---------------- launch 3: permute (blocks 0..NPERM-1) + gemm tiles NT2..NTILE-1 ----------------
__global__ void __launch_bounds__(256) perm_gemm_kernel(const int* __restrict__ er,
                                                        const int* __restrict__ ec,
                                                        const float* __restrict__ X,
                                                        const float* __restrict__ W,
                                                        const float* __restrict__ Bias) {
    extern __shared__ char smem[];
    const int tid = threadIdx.x;

    if (blockIdx.x >= NPERM) {
        gemm_tile(smem, NT2 + (blockIdx.x - NPERM), X, W, Bias);
        return;
    }

    int base = blockIdx.x * 2048 + tid * 8;
    if (base + 7 < NE) {
        int4 r0 = *(const int4*)(er + base);
        int4 r1 = *(const int4*)(er + base + 4);
        int4 c0 = *(const int4*)(ec + base);
        int4 c1 = *(const int4*)(ec + base + 4);
        int p0 = atomicAdd(&g_cur[r0.x], 1);
        int p1 = atomicAdd(&g_cur[r0.y], 1);
        int p2 = atomicAdd(&g_cur[r0.z], 1);
        int p3 = atomicAdd(&g_cur[r0.w], 1);
        int p4 = atomicAdd(&g_cur[r1.x], 1);
        int p5 = atomicAdd(&g_cur[r1.y], 1);
        int p6 = atomicAdd(&g_cur[r1.z], 1);
        int p7 = atomicAdd(&g_cur[r1.w], 1);
        g_col[p0] = c0.x; g_col[p1] = c0.y; g_col[p2] = c0.z; g_col[p3] = c0.w;
        g_col[p4] = c1.x; g_col[p5] = c1.y; g_col[p6] = c1.z; g_col[p7] = c1.w;
    } else {
        for (int e = base; e < NE; e++) {
            int pos = atomicAdd(&g_cur[er[e]], 1);
            g_col[pos] = ec[e];
        }
    }
}

// ---------------- launch 4: gather — R9-exact (8-edge, two quad trees) ----------------
__device__ __forceinline__ void quad_acc(float4& acc, uint2 v0, uint2 v1, uint2 v2, uint2 v3) {
    __half2 s0 = __hadd2(*(__half2*)&v0.x, *(__half2*)&v1.x);
    __half2 s1 = __hadd2(*(__half2*)&v0.y, *(__half2*)&v1.y);
    __half2 t0 = __hadd2(*(__half2*)&v2.x, *(__half2*)&v3.x);
    __half2 t1 = __hadd2(*(__half2*)&v2.y, *(__half2*)&v3.y);
    __half2 u0 = __hadd2(s0, t0);
    __half2 u1 = __hadd2(s1, t1);
    float2 f0 = __half22float2(u0);
    float2 f1 = __half22float2(u1);
    acc.x += f0.x; acc.y += f0.y; acc.z += f1.x; acc.w += f1.y;
}

__global__ void __launch_bounds__(256) gather_kernel(float* __restrict__ out) {
    int warp = (blockIdx.x * 256 + threadIdx.x) >> 5;
    int lane = threadIdx.x & 31;
    if (warp >= NN) return;
    int beg = g_off[warp];
    int end = g_off[warp + 1];

    const __half* hb = g_hf + lane * 4;

    // self-loop, flushed to fp32
    uint2 sv = *(const uint2*)(hb + (size_t)warp * DD);
    float2 sf0 = __half22float2(*(__half2*)&sv.x);
    float2 sf1 = __half22float2(*(__half2*)&sv.y);
    float4 acc = make_float4(sf0.x, sf0.y, sf1.x, sf1.y);

    int e = beg;
    for (; e + 8 <= end; e += 8) {
        int c0 = g_col[e + 0], c1 = g_col[e + 1], c2 = g_col[e + 2], c3 = g_col[e + 3];
        int c4 = g_col[e + 4], c5 = g_col[e + 5], c6 = g_col[e + 6], c7 = g_col[e + 7];
        uint2 v0 = *(const uint2*)(hb + (size_t)c0 * DD);
        uint2 v1 = *(const uint2*)(hb + (size_t)c1 * DD);
        uint2 v2 = *(const uint2*)(hb + (size_t)c2 * DD);
        uint2 v3 = *(const uint2*)(hb + (size_t)c3 * DD);
        uint2 v4 = *(const uint2*)(hb + (size_t)c4 * DD);
        uint2 v5 = *(const uint2*)(hb + (size_t)c5 * DD);
        uint2 v6 = *(const uint2*)(hb + (size_t)c6 * DD);
        uint2 v7 = *(const uint2*)(hb + (size_t)c7 * DD);
        quad_acc(acc, v0, v1, v2, v3);
        quad_acc(acc, v4, v5, v6, v7);
    }
    for (; e + 4 <= end; e += 4) {
        int c0 = g_col[e + 0], c1 = g_col[e + 1], c2 = g_col[e + 2], c3 = g_col[e + 3];
        uint2 v0 = *(const uint2*)(hb + (size_t)c0 * DD);
        uint2 v1 = *(const uint2*)(hb + (size_t)c1 * DD);
        uint2 v2 = *(const uint2*)(hb + (size_t)c2 * DD);
        uint2 v3 = *(const uint2*)(hb + (size_t)c3 * DD);
        quad_acc(acc, v0, v1, v2, v3);
    }
    for (; e < end; e++) {
        uint2 v = *(const uint2*)(hb + (size_t)g_col[e] * DD);
        float2 f0 = __half22float2(*(__half2*)&v.x);
        float2 f1 = __half22float2(*(__half2*)&v.y);
        acc.x += f0.x; acc.y += f0.y; acc.z += f1.x; acc.w += f1.y;
    }

    float inv = 1.0f / (float)(end - beg + 1);
    acc.x = fmaxf(acc.x * inv, 0.f);
    acc.y = fmaxf(acc.y * inv, 0.f);
    acc.z = fmaxf(acc.z * inv, 0.f);
    acc.w = fmaxf(acc.w * inv, 0.f);
    *(float4*)(out + (size_t)warp * DD + lane * 4) = acc;
}

extern "C" void kernel_launch(void* const* d_in, const int* in_sizes, int n_in,
                              void* d_out, int out_size) {
    const float* x  = (const float*)d_in[0];
    const float* W  = (const float*)d_in[1];
    const float* b  = (const float*)d_in[2];
    const int* er   = (const int*)d_in[3];
    const int* ec   = (const int*)d_in[4];
    float* out      = (float*)d_out;

    hist_kernel<<<NHB, 256>>>(er);

    cudaFuncSetAttribute(scan_gemm_kernel, cudaFuncAttributeMaxDynamicSharedMemorySize, GSMEM);
    scan_gemm_kernel<<<NB + NT2, 256, GSMEM>>>(x, W, b);

    cudaFuncSetAttribute(perm_gemm_kernel, cudaFuncAttributeMaxDynamicSharedMemorySize, GSMEM);
    perm_gemm_kernel<<<NPERM + NT3, 256, GSMEM>>>(er, ec, x, W, b);

    gather_kernel<<<(NN * 32 + 255) / 256, 256>>>(out);
}

// round 13
// speedup vs baseline: 1.2162x; 1.1490x over previous
#include <cuda_runtime.h>
#include <cuda_bf16.h>
#include <cuda_fp16.h>
#include <cstdint>

#define NN 100000
#define NE 1600000
#define DD 128
#define NB ((NN + 1023) / 1024)       // 98 scan blocks
#define NTILE ((NN + 127) / 128)      // 782 GEMM tiles
#define NHB ((NE + 2047) / 2048)      // 782 histrank blocks (ILP8)
#define GCOLSZ (NE + 4 * NN)          // padded CSR capacity (2.0M)
#define NFILL ((GCOLSZ + 8191) / 8192) // 245 fill blocks (32 ints/thread)
#define NSPEC (NFILL + NHB)
#define ROWPAD 136                    // fp16 elems per SMEM row (272B, conflict-free)

typedef unsigned long long ull;

// ---------------- scratch (__device__ globals; zero-initialized at load) ----------------
__device__ __half g_hf[(size_t)(NN + 1) * DD]; // +1: row NN is permanently zero (pad target)
__device__ int    g_deg[NN];               // invariant: 0 at kernel_launch entry
__device__ int    g_rdeg[NN];              // true degree (for normalization)
__device__ int    g_off[NN + 1];           // padded (ceil4) offsets
__device__ int    g_rank[NE];              // edge rank within its row
__device__ int    g_col[GCOLSZ];           // padded CSR cols
__device__ ull    g_lb[NB];                // lookback state: (state<<32)|value

__device__ __forceinline__ uint32_t smem_u32(const void* p) {
    uint32_t a;
    asm("{ .reg .u64 t; cvta.to.shared.u64 t, %1; cvt.u32.u64 %0, t; }" : "=r"(a) : "l"(p));
    return a;
}

// ---------------- HMMA helpers + GEMM tile body (fp16 single-term) ----------------
__device__ __forceinline__ void mma_f16(float* c, const uint32_t* a, uint32_t b0, uint32_t b1) {
    asm volatile(
        "mma.sync.aligned.m16n8k16.row.col.f32.f16.f16.f32 "
        "{%0,%1,%2,%3}, {%4,%5,%6,%7}, {%8,%9}, {%0,%1,%2,%3};"
        : "+f"(c[0]), "+f"(c[1]), "+f"(c[2]), "+f"(c[3])
        : "r"(a[0]), "r"(a[1]), "r"(a[2]), "r"(a[3]), "r"(b0), "r"(b1));
}
__device__ __forceinline__ void ldm_x4(uint32_t* a, uint32_t addr) {
    asm volatile("ldmatrix.sync.aligned.m8n8.x4.shared.b16 {%0,%1,%2,%3}, [%4];"
                 : "=r"(a[0]), "=r"(a[1]), "=r"(a[2]), "=r"(a[3]) : "r"(addr));
}

#define GSMEM (128 * ROWPAD * 2)   // single fp16 A buffer, 34816 B

__device__ __forceinline__ void gemm_tile(char* smem, int tile,
                                          const float* __restrict__ X,
                                          const float* __restrict__ W,
                                          const float* __restrict__ Bias) {
    __half* Ah = (__half*)smem;

    const int tid = threadIdx.x;
    const int w = tid >> 5;
    const int lane = tid & 31;
    const int r0 = tile * 128;

#pragma unroll
    for (int it = 0; it < 16; it++) {
        int idx = tid + it * 256;          // 4096 float4
        int row = idx >> 5;
        int kq  = idx & 31;
        float4 v = make_float4(0.f, 0.f, 0.f, 0.f);
        if (r0 + row < NN) v = *(const float4*)(X + (size_t)(r0 + row) * DD + kq * 4);
        __half2 h01 = __float22half2_rn(make_float2(v.x, v.y));
        __half2 h23 = __float22half2_rn(make_float2(v.z, v.w));
        uint32_t u01 = *(uint32_t*)&h01;
        uint32_t u23 = *(uint32_t*)&h23;
        *(ull*)(Ah + row * ROWPAD + kq * 4) = ((ull)u23 << 32) | u01;
    }

    uint32_t bh[2][8][2];
#pragma unroll
    for (int t = 0; t < 2; t++)
#pragma unroll
        for (int ks = 0; ks < 8; ks++)
#pragma unroll
            for (int r = 0; r < 2; r++) {
                int n = w * 16 + t * 8 + (lane >> 2);
                int k = ks * 16 + r * 8 + (lane & 3) * 2;
                float2 v = *(const float2*)(W + n * DD + k);
                __half2 h = __float22half2_rn(v);
                bh[t][ks][r] = *(uint32_t*)&h;
            }

    const int t2 = lane & 3;
    const int g  = lane >> 2;
    float2 bias0 = *(const float2*)(Bias + w * 16 + t2 * 2);
    float2 bias1 = *(const float2*)(Bias + w * 16 + 8 + t2 * 2);

    __syncthreads();

    const uint32_t ah_base = smem_u32(Ah);
    const uint32_t rowoff =
        ((((lane >> 3) & 1) * 8 + (lane & 7)) * ROWPAD + (lane >> 4) * 8) * 2;

#pragma unroll
    for (int mt = 0; mt < 8; mt++) {
        float acc0[4] = {0.f, 0.f, 0.f, 0.f};
        float acc1[4] = {0.f, 0.f, 0.f, 0.f};
#pragma unroll
        for (int ks = 0; ks < 8; ks++) {
            uint32_t off = (uint32_t)(mt * 16 * ROWPAD * 2 + ks * 32) + rowoff;
            uint32_t ah[4];
            ldm_x4(ah, ah_base + off);
            mma_f16(acc0, ah, bh[0][ks][0], bh[0][ks][1]);
            mma_f16(acc1, ah, bh[1][ks][0], bh[1][ks][1]);
        }
        int row = r0 + mt * 16 + g;
        int col0 = w * 16 + t2 * 2;
        if (row < NN) {
            __half* q = g_hf + (size_t)row * DD;
            *(__half2*)(q + col0) =
                __float22half2_rn(make_float2(acc0[0] + bias0.x, acc0[1] + bias0.y));
            *(__half2*)(q + col0 + 8) =
                __float22half2_rn(make_float2(acc1[0] + bias1.x, acc1[1] + bias1.y));
        }
        if (row + 8 < NN) {
            __half* q = g_hf + (size_t)(row + 8) * DD;
            *(__half2*)(q + col0) =
                __float22half2_rn(make_float2(acc0[2] + bias0.x, acc0[3] + bias0.y));
            *(__half2*)(q + col0 + 8) =
                __float22half2_rn(make_float2(acc1[2] + bias1.x, acc1[3] + bias1.y));
        }
    }
}

// ---------------- launch 1: fill + histrank + ALL gemm tiles (Bresenham interleave) ----------------
__global__ void __launch_bounds__(256) fused1_kernel(const int* __restrict__ er,
                                                     const float* __restrict__ X,
                                                     const float* __restrict__ W,
                                                     const float* __restrict__ Bias) {
    extern __shared__ char smem[];
    const int tid = threadIdx.x;
    const int bid = blockIdx.x;
    const int total = NSPEC + NTILE;
    int gA = (int)(((long long)bid * NTILE) / total);
    int gB = (int)(((long long)(bid + 1) * NTILE) / total);
    if (gB > gA) {                          // GEMM block
        gemm_tile(smem, gA, X, W, Bias);
        return;
    }
    int sidx = bid - gA;

    if (sidx < NFILL) {
        // fill g_col with NN (zero-row index); pads survive, rest overwritten by permute
        if (sidx == 0 && tid < NB) g_lb[tid] = 0ull;
        int base = sidx * 8192 + tid * 4;
        const int4 pad = make_int4(NN, NN, NN, NN);
#pragma unroll
        for (int i = 0; i < 8; i++) {
            int idx = base + i * 1024;
            if (idx + 3 < GCOLSZ) *(int4*)(g_col + idx) = pad;
            else for (int j = idx; j < GCOLSZ; j++) g_col[j] = NN;
        }
        return;
    }

    // histrank: 8 edges per thread; capture ranks
    int hbid = sidx - NFILL;
    int base = hbid * 2048 + tid * 8;
    if (base + 7 < NE) {
        int4 a = *(const int4*)(er + base);
        int4 c = *(const int4*)(er + base + 4);
        int k0 = atomicAdd(&g_deg[a.x], 1);
        int k1 = atomicAdd(&g_deg[a.y], 1);
        int k2 = atomicAdd(&g_deg[a.z], 1);
        int k3 = atomicAdd(&g_deg[a.w], 1);
        int k4 = atomicAdd(&g_deg[c.x], 1);
        int k5 = atomicAdd(&g_deg[c.y], 1);
        int k6 = atomicAdd(&g_deg[c.z], 1);
        int k7 = atomicAdd(&g_deg[c.w], 1);
        *(int4*)(g_rank + base)     = make_int4(k0, k1, k2, k3);
        *(int4*)(g_rank + base + 4) = make_int4(k4, k5, k6, k7);
    } else {
        for (int e = base; e < NE; e++) g_rank[e] = atomicAdd(&g_deg[er[e]], 1);
    }
}

// ---------------- launch 2: scan over ceil4(deg) + save true deg + reset ----------------
__global__ void __launch_bounds__(256) scan_kernel() {
    __shared__ int sh[256];
    __shared__ int s_prefix;
    const int bid = blockIdx.x;
    const int tid = threadIdx.x;
    const int base = bid * 1024 + tid * 4;

    int pads[4];
    int s = 0;
#pragma unroll
    for (int k = 0; k < 4; k++) {
        int i = base + k;
        int d = (i < NN) ? g_deg[i] : 0;
        if (i < NN) { g_rdeg[i] = d; g_deg[i] = 0; }   // save + restore invariant
        pads[k] = (d + 3) & ~3;
        s += pads[k];
    }
    sh[tid] = s;
    __syncthreads();
    for (int off = 1; off < 256; off <<= 1) {
        int t = (tid >= off) ? sh[tid - off] : 0;
        __syncthreads();
        sh[tid] += t;
        __syncthreads();
    }
    const int T = sh[255];
    const int excl_local = sh[tid] - s;

    if (tid == 0) {
        ull pub = ((bid == 0) ? (2ull << 32) : (1ull << 32)) | (unsigned)T;
        atomicExch(&g_lb[bid], pub);
        if (bid == 0) s_prefix = 0;
    }
    if (bid > 0 && tid < 32) {
        int sum = 0;
        int wb = bid;
        while (true) {
            int idx = wb - 32 + tid;
            ull v;
            unsigned st;
            while (true) {
                v = (idx >= 0) ? atomicOr(&g_lb[idx], 0ull) : (2ull << 32);
                st = (unsigned)(v >> 32);
                if (__all_sync(0xffffffffu, st != 0)) break;
            }
            unsigned pmask = __ballot_sync(0xffffffffu, st == 2);
            if (pmask) {
                int lead = 31 - __clz(pmask);
                int c = (tid >= lead) ? (int)(v & 0xffffffffu) : 0;
#pragma unroll
                for (int o = 16; o; o >>= 1) c += __shfl_down_sync(0xffffffffu, c, o);
                if (tid == 0) sum += c;
                break;
            } else {
                int c = (int)(v & 0xffffffffu);
#pragma unroll
                for (int o = 16; o; o >>= 1) c += __shfl_down_sync(0xffffffffu, c, o);
                if (tid == 0) sum += c;
                wb -= 32;
            }
        }
        if (tid == 0) {
            s_prefix = sum;
            atomicExch(&g_lb[bid], (2ull << 32) | (unsigned)(sum + T));
        }
    }
    __syncthreads();

    int excl = excl_local + s_prefix;
#pragma unroll
    for (int k = 0; k < 4; k++) {
        int i = base + k;
        if (i < NN) g_off[i] = excl;
        excl += pads[k];
    }
    if (bid == NB - 1 && tid == 255) g_off[NN] = excl;
}

// ---------------- launch 3: streaming permute (NO atomics) ----------------
__global__ void __launch_bounds__(256) permute_kernel(const int* __restrict__ er,
                                                      const int* __restrict__ ec) {
    int base = (blockIdx.x * 256 + threadIdx.x) * 8;
    if (base + 7 < NE) {
        int4 r0 = *(const int4*)(er + base);
        int4 r1 = *(const int4*)(er + base + 4);
        int4 c0 = *(const int4*)(ec + base);
        int4 c1 = *(const int4*)(ec + base + 4);
        int4 k0 = *(const int4*)(g_rank + base);
        int4 k1 = *(const int4*)(g_rank + base + 4);
        g_col[g_off[r0.x] + k0.x] = c0.x;
        g_col[g_off[r0.y] + k0.y] = c0.y;
        g_col[g_off[r0.z] + k0.z] = c0.z;
        g_col[g_off[r0.w] + k0.w] = c0.w;
        g_col[g_off[r1.x] + k1.x] = c1.x;
        g_col[g_off[r1.y] + k1.y] = c1.y;
        g_col[g_off[r1.z] + k1.z] = c1.z;
        g_col[g_off[r1.w] + k1.w] = c1.w;
    } else {
        for (int e = base; e < NE; e++)
            g_col[g_off[er[e]] + g_rank[e]] = ec[e];
    }
}

// ---------------- launch 4: gather — 8-edge unroll, two quad trees, padded (no tail) ----------------
__device__ __forceinline__ void quad_acc(float4& acc, uint2 v0, uint2 v1, uint2 v2, uint2 v3) {
    __half2 s0 = __hadd2(*(__half2*)&v0.x, *(__half2*)&v1.x);
    __half2 s1 = __hadd2(*(__half2*)&v0.y, *(__half2*)&v1.y);
    __half2 t0 = __hadd2(*(__half2*)&v2.x, *(__half2*)&v3.x);
    __half2 t1 = __hadd2(*(__half2*)&v2.y, *(__half2*)&v3.y);
    __half2 u0 = __hadd2(s0, t0);
    __half2 u1 = __hadd2(s1, t1);
    float2 f0 = __half22float2(u0);
    float2 f1 = __half22float2(u1);
    acc.x += f0.x; acc.y += f0.y; acc.z += f1.x; acc.w += f1.y;
}

__global__ void __launch_bounds__(256) gather_kernel(float* __restrict__ out) {
    int warp = (blockIdx.x * 256 + threadIdx.x) >> 5;
    int lane = threadIdx.x & 31;
    if (warp >= NN) return;
    int beg = g_off[warp];
    int end = g_off[warp + 1];           // padded extent (multiple of 4 entries)
    int deg = g_rdeg[warp];

    const __half* hb = g_hf + lane * 4;

    // self-loop, flushed to fp32
    uint2 sv = *(const uint2*)(hb + (size_t)warp * DD);
    float2 sf0 = __half22float2(*(__half2*)&sv.x);
    float2 sf1 = __half22float2(*(__half2*)&sv.y);
    float4 acc = make_float4(sf0.x, sf0.y, sf1.x, sf1.y);

    int e = beg;
    for (; e + 8 <= end; e += 8) {
        int c0 = g_col[e + 0], c1 = g_col[e + 1], c2 = g_col[e + 2], c3 = g_col[e + 3];
        int c4 = g_col[e + 4], c5 = g_col[e + 5], c6 = g_col[e + 6], c7 = g_col[e + 7];
        uint2 v0 = *(const uint2*)(hb + (size_t)c0 * DD);
        uint2 v1 = *(const uint2*)(hb + (size_t)c1 * DD);
        uint2 v2 = *(const uint2*)(hb + (size_t)c2 * DD);
        uint2 v3 = *(const uint2*)(hb + (size_t)c3 * DD);
        uint2 v4 = *(const uint2*)(hb + (size_t)c4 * DD);
        uint2 v5 = *(const uint2*)(hb + (size_t)c5 * DD);
        uint2 v6 = *(const uint2*)(hb + (size_t)c6 * DD);
        uint2 v7 = *(const uint2*)(hb + (size_t)c7 * DD);
        quad_acc(acc, v0, v1, v2, v3);
        quad_acc(acc, v4, v5, v6, v7);
    }
    if (e < end) {                       // exactly one 4-group remains (padded)
        int c0 = g_col[e + 0], c1 = g_col[e + 1], c2 = g_col[e + 2], c3 = g_col[e + 3];
        uint2 v0 = *(const uint2*)(hb + (size_t)c0 * DD);
        uint2 v1 = *(const uint2*)(hb + (size_t)c1 * DD);
        uint2 v2 = *(const uint2*)(hb + (size_t)c2 * DD);
        uint2 v3 = *(const uint2*)(hb + (size_t)c3 * DD);
        quad_acc(acc, v0, v1, v2, v3);
    }

    float inv = 1.0f / (float)(deg + 1);
    acc.x = fmaxf(acc.x * inv, 0.f);
    acc.y = fmaxf(acc.y * inv, 0.f);
    acc.z = fmaxf(acc.z * inv, 0.f);
    acc.w = fmaxf(acc.w * inv, 0.f);
    *(float4*)(out + (size_t)warp * DD + lane * 4) = acc;
}

extern "C" void kernel_launch(void* const* d_in, const int* in_sizes, int n_in,
                              void* d_out, int out_size) {
    const float* x  = (const float*)d_in[0];
    const float* W  = (const float*)d_in[1];
    const float* b  = (const float*)d_in[2];
    const int* er   = (const int*)d_in[3];
    const int* ec   = (const int*)d_in[4];
    float* out      = (float*)d_out;

    cudaFuncSetAttribute(fused1_kernel, cudaFuncAttributeMaxDynamicSharedMemorySize, GSMEM);
    fused1_kernel<<<NSPEC + NTILE, 256, GSMEM>>>(er, x, W, b);

    scan_kernel<<<NB, 256>>>();
    permute_kernel<<<(NE / 8 + 255) / 256, 256>>>(er, ec);
    gather_kernel<<<(NN * 32 + 255) / 256, 256>>>(out);
}